// round 12
// baseline (speedup 1.0000x reference)
#include <cuda_runtime.h>
#include <cuda_fp16.h>
#include <cstdint>

#define DINLINE __device__ __forceinline__

// ---------------- helpers ----------------

DINLINE uint32_t smem_u32(const void* p) {
    uint32_t a;
    asm("{ .reg .u64 t; cvta.to.shared.u64 t, %1; cvt.u32.u64 %0, t; }"
        : "=r"(a) : "l"(p));
    return a;
}

DINLINE void ldsm_x4(uint32_t& r0, uint32_t& r1, uint32_t& r2, uint32_t& r3,
                     uint32_t addr) {
    asm volatile("ldmatrix.sync.aligned.m8n8.x4.shared.b16 {%0,%1,%2,%3}, [%4];"
                 : "=r"(r0), "=r"(r1), "=r"(r2), "=r"(r3) : "r"(addr));
}

DINLINE void ldsm_x4_trans(uint32_t& r0, uint32_t& r1, uint32_t& r2, uint32_t& r3,
                           uint32_t addr) {
    asm volatile("ldmatrix.sync.aligned.m8n8.x4.trans.shared.b16 {%0,%1,%2,%3}, [%4];"
                 : "=r"(r0), "=r"(r1), "=r"(r2), "=r"(r3) : "r"(addr));
}

DINLINE void mma16816(float* c, const uint32_t* a, uint32_t b0, uint32_t b1) {
    asm volatile(
        "mma.sync.aligned.m16n8k16.row.col.f32.f16.f16.f32 "
        "{%0,%1,%2,%3}, {%4,%5,%6,%7}, {%8,%9}, {%0,%1,%2,%3};"
        : "+f"(c[0]), "+f"(c[1]), "+f"(c[2]), "+f"(c[3])
        : "r"(a[0]), "r"(a[1]), "r"(a[2]), "r"(a[3]), "r"(b0), "r"(b1));
}

DINLINE float fsigmoid(float x) {
    // input is already score/16 (scale folded into Q staging):
    // sigmoid(score/8) = 0.5 + 0.5 * tanh(score/16); single MUFU + one FFMA
    float t;
    asm("tanh.approx.f32 %0, %1;" : "=f"(t) : "f"(x));
    return fmaf(0.5f, t, 0.5f);
}

DINLINE uint32_t packh2(float a, float b) {
    __half2 h = __floats2half2_rn(a, b);
    return *reinterpret_cast<uint32_t*>(&h);
}

// ---------------- problem constants ----------------
// B=4, H=16, S=2048, D=64.  64 heads x 8 q-tiles of 256 rows = 512 CTAs.
// 16 warps/CTA, M=16 q-rows per warp. KTILE=128 keys per iteration with a
// single end-of-iteration barrier; K/V staging for the next tile is done
// DIRECTLY into the free buffer mid-iteration (no cross-iter registers).
static constexpr int S_LEN  = 2048;
static constexpr int D_DIM  = 64;
static constexpr int QTILE  = 256;
static constexpr int KTILE  = 128;
static constexpr int NKT    = S_LEN / KTILE;   // 16
static constexpr int NCHUNK = KTILE / 16;      // 8 (16-key chunks)
static constexpr int NWARP  = 16;
static constexpr int NTHR   = NWARP * 32;      // 512

// SMEM (halves, row stride 72 => 144B rows, conflict-free for ldmatrix)
static constexpr int STRIDE   = 72;
static constexpr int TILE_B   = KTILE * STRIDE * 2;      // 18432 bytes (128x64 f16 tile)
static constexpr int BUF_B    = 2 * TILE_B;              // K + V per stage: 36864
static constexpr int SMEM_BYTES = 2 * BUF_B;             // 73728 (double buffer)

__global__ void __launch_bounds__(NTHR, 1) sigattn_kernel(
    const float* __restrict__ gq, const float* __restrict__ gk,
    const float* __restrict__ gv, float* __restrict__ gout)
{
    extern __shared__ char smem[];
    const uint32_t sb = smem_u32(smem);
    const int tid  = threadIdx.x;
    const int wid  = tid >> 5;
    const int lane = tid & 31;

    const int bx = blockIdx.x;
    const int qt = bx & 7;           // q-tile within head
    const int bh = bx >> 3;          // flattened (b,h)
    const size_t head_base = (size_t)bh * S_LEN * D_DIM;
    const float* qb = gq + head_base + (size_t)qt * QTILE * D_DIM;
    const float* kb = gk + head_base;
    const float* vb = gv + head_base;
    float*       ob = gout + head_base + (size_t)qt * QTILE * D_DIM;

    // ---- stage Q (fp32 -> f16, pre-scaled by 1/16) into SMEM ----
    {
        const float SC = 0.0625f;           // folds the /8 sdpa scale and /2 of tanh
        int row = tid >> 1;                 // 0..255
        int c0  = (tid & 1) * 32;           // 0 or 32
        const float4* src = reinterpret_cast<const float4*>(qb + (size_t)row * D_DIM + c0);
        uint32_t* dst = reinterpret_cast<uint32_t*>(smem) + (row * STRIDE + c0) / 2;
        #pragma unroll
        for (int i = 0; i < 8; i++) {
            float4 f = src[i];
            dst[2 * i]     = packh2(f.x * SC, f.y * SC);
            dst[2 * i + 1] = packh2(f.z * SC, f.w * SC);
        }
    }
    __syncthreads();

    const int idx = lane & 15;
    const int seg = lane >> 4;          // 0/1

    // Q fragments: qf[kstep][4] regs, warp rows 16*wid .. +15
    uint32_t qf[4][4];
    #pragma unroll
    for (int s = 0; s < 4; s++) {
        uint32_t addr = sb + (uint32_t)(((16 * wid + idx) * STRIDE) + 16 * s + 8 * seg) * 2;
        ldsm_x4(qf[s][0], qf[s][1], qf[s][2], qf[s][3], addr);
    }
    __syncthreads();   // Q fully in registers before K/V overwrite SMEM

    // per-thread K/V staging coordinates (128x64 tile, 512 threads:
    // each thread moves 16 consecutive floats of K and of V)
    const int kvrow = tid >> 2;             // 0..127
    const int kvc0  = (tid & 3) * 16;       // 0,16,32,48
    const int kv_soff = (kvrow * STRIDE + kvc0) / 2;   // u32 index into tile
    const size_t kv_gbase = (size_t)kvrow * D_DIM + kvc0;

    // ---- preload tile 0 into buffer 0 ----
    {
        const float4* ksrc = reinterpret_cast<const float4*>(kb + kv_gbase);
        const float4* vsrc = reinterpret_cast<const float4*>(vb + kv_gbase);
        uint32_t* kd = reinterpret_cast<uint32_t*>(smem) + kv_soff;
        uint32_t* vd = reinterpret_cast<uint32_t*>(smem + TILE_B) + kv_soff;
        #pragma unroll
        for (int i = 0; i < 4; i++) {
            float4 kf = ksrc[i], vf = vsrc[i];
            kd[2 * i] = packh2(kf.x, kf.y); kd[2 * i + 1] = packh2(kf.z, kf.w);
            vd[2 * i] = packh2(vf.x, vf.y); vd[2 * i + 1] = packh2(vf.z, vf.w);
        }
    }
    __syncthreads();

    // ---- O accumulators: 8 d-tiles x 4 fp32 ----
    float oc[8][4];
    #pragma unroll
    for (int j = 0; j < 8; j++)
        #pragma unroll
        for (int r = 0; r < 4; r++) oc[j][r] = 0.0f;

    // loop-invariant piece of B-side ldmatrix addresses
    const uint32_t lds_base = sb + (uint32_t)((idx * STRIDE + 8 * seg) * 2);

    // one 16-key chunk: QK -> (V ldsm early) -> sigmoid -> PV
    auto do_chunk = [&](int t, uint32_t cur_off) {
        float sc0[4] = {0.f, 0.f, 0.f, 0.f};
        float sc1[4] = {0.f, 0.f, 0.f, 0.f};
        #pragma unroll
        for (int s = 0; s < 4; s++) {
            uint32_t r0, r1, r2, r3;
            uint32_t addr = lds_base + cur_off +
                (uint32_t)((16 * t * STRIDE + 16 * s) * 2);
            ldsm_x4(r0, r1, r2, r3, addr);
            mma16816(sc0, qf[s], r0, r2);
            mma16816(sc1, qf[s], r1, r3);
        }
        // V fragments issued before the MUFU chain so trans-ldsm latency hides
        uint32_t vf[4][4];
        #pragma unroll
        for (int m = 0; m < 4; m++) {
            uint32_t addr = lds_base + cur_off + (uint32_t)TILE_B +
                (uint32_t)((16 * t * STRIDE + 16 * m) * 2);
            ldsm_x4_trans(vf[m][0], vf[m][1], vf[m][2], vf[m][3], addr);
        }
        uint32_t pf[4];
        pf[0] = packh2(fsigmoid(sc0[0]), fsigmoid(sc0[1]));
        pf[1] = packh2(fsigmoid(sc0[2]), fsigmoid(sc0[3]));
        pf[2] = packh2(fsigmoid(sc1[0]), fsigmoid(sc1[1]));
        pf[3] = packh2(fsigmoid(sc1[2]), fsigmoid(sc1[3]));
        #pragma unroll
        for (int m = 0; m < 4; m++) {
            mma16816(oc[2 * m],     pf, vf[m][0], vf[m][1]);
            mma16816(oc[2 * m + 1], pf, vf[m][2], vf[m][3]);
        }
    };

    for (int kt = 0; kt < NKT; kt++) {
        const uint32_t cur_off  = (uint32_t)((kt & 1) * BUF_B);
        const uint32_t next_off = (uint32_t)(((kt + 1) & 1) * BUF_B);

        // chunks 0-1
        do_chunk(0, cur_off);
        do_chunk(1, cur_off);

        // ---- mid-iteration staging of tile kt+1 directly into free buffer:
        //      the buffer was last read in iter kt-1 (guarded by that iter's
        //      barrier); reads of it happen in iter kt+1 after this iter's
        //      end barrier. LSU is idle here; other warps keep tensor busy. ----
        if (kt + 1 < NKT) {
            size_t gofs = (size_t)(kt + 1) * KTILE * D_DIM + kv_gbase;
            const float4* ksrc = reinterpret_cast<const float4*>(kb + gofs);
            const float4* vsrc = reinterpret_cast<const float4*>(vb + gofs);
            float4 kf0 = ksrc[0], kf1 = ksrc[1], kf2 = ksrc[2], kf3 = ksrc[3];
            float4 vf0 = vsrc[0], vf1 = vsrc[1], vf2 = vsrc[2], vf3 = vsrc[3];
            uint32_t* kd = reinterpret_cast<uint32_t*>(smem + next_off) + kv_soff;
            uint32_t* vd = reinterpret_cast<uint32_t*>(smem + next_off + TILE_B) + kv_soff;
            kd[0] = packh2(kf0.x, kf0.y); kd[1] = packh2(kf0.z, kf0.w);
            kd[2] = packh2(kf1.x, kf1.y); kd[3] = packh2(kf1.z, kf1.w);
            kd[4] = packh2(kf2.x, kf2.y); kd[5] = packh2(kf2.z, kf2.w);
            kd[6] = packh2(kf3.x, kf3.y); kd[7] = packh2(kf3.z, kf3.w);
            vd[0] = packh2(vf0.x, vf0.y); vd[1] = packh2(vf0.z, vf0.w);
            vd[2] = packh2(vf1.x, vf1.y); vd[3] = packh2(vf1.z, vf1.w);
            vd[4] = packh2(vf2.x, vf2.y); vd[5] = packh2(vf2.z, vf2.w);
            vd[6] = packh2(vf3.x, vf3.y); vd[7] = packh2(vf3.z, vf3.w);
        }

        // chunks 2-7
        #pragma unroll
        for (int t = 2; t < NCHUNK; t++)
            do_chunk(t, cur_off);

        // single barrier per iteration: everyone done reading cur (freed for
        // staging in iter kt+1) AND this iter's staging visible for kt+1 reads
        __syncthreads();
    }

    // ---- epilogue: write O (fp32) ----
    {
        const int g  = lane >> 2;
        const int tg = lane & 3;
        const int r0 = 16 * wid + g;
        const int r1 = r0 + 8;
        #pragma unroll
        for (int j = 0; j < 8; j++) {
            int c = 8 * j + 2 * tg;
            *reinterpret_cast<float2*>(ob + (size_t)r0 * D_DIM + c) =
                make_float2(oc[j][0], oc[j][1]);
            *reinterpret_cast<float2*>(ob + (size_t)r1 * D_DIM + c) =
                make_float2(oc[j][2], oc[j][3]);
        }
    }
}

extern "C" void kernel_launch(void* const* d_in, const int* in_sizes, int n_in,
                              void* d_out, int out_size) {
    (void)in_sizes; (void)n_in; (void)out_size;
    const float* q = (const float*)d_in[0];
    const float* k = (const float*)d_in[1];
    const float* v = (const float*)d_in[2];
    float* out = (float*)d_out;

    cudaFuncSetAttribute(sigattn_kernel,
                         cudaFuncAttributeMaxDynamicSharedMemorySize, SMEM_BYTES);
    sigattn_kernel<<<512, NTHR, SMEM_BYTES>>>(q, k, v, out);
}

// round 13
// speedup vs baseline: 1.1402x; 1.1402x over previous
#include <cuda_runtime.h>
#include <cuda_fp16.h>
#include <cstdint>

#define DINLINE __device__ __forceinline__

// ---------------- helpers ----------------

DINLINE uint32_t smem_u32(const void* p) {
    uint32_t a;
    asm("{ .reg .u64 t; cvta.to.shared.u64 t, %1; cvt.u32.u64 %0, t; }"
        : "=r"(a) : "l"(p));
    return a;
}

DINLINE void ldsm_x4(uint32_t& r0, uint32_t& r1, uint32_t& r2, uint32_t& r3,
                     uint32_t addr) {
    asm volatile("ldmatrix.sync.aligned.m8n8.x4.shared.b16 {%0,%1,%2,%3}, [%4];"
                 : "=r"(r0), "=r"(r1), "=r"(r2), "=r"(r3) : "r"(addr));
}

DINLINE void ldsm_x4_trans(uint32_t& r0, uint32_t& r1, uint32_t& r2, uint32_t& r3,
                           uint32_t addr) {
    asm volatile("ldmatrix.sync.aligned.m8n8.x4.trans.shared.b16 {%0,%1,%2,%3}, [%4];"
                 : "=r"(r0), "=r"(r1), "=r"(r2), "=r"(r3) : "r"(addr));
}

// fp32-accumulator HMMA (PV GEMM)
DINLINE void mma16816(float* c, const uint32_t* a, uint32_t b0, uint32_t b1) {
    asm volatile(
        "mma.sync.aligned.m16n8k16.row.col.f32.f16.f16.f32 "
        "{%0,%1,%2,%3}, {%4,%5,%6,%7}, {%8,%9}, {%0,%1,%2,%3};"
        : "+f"(c[0]), "+f"(c[1]), "+f"(c[2]), "+f"(c[3])
        : "r"(a[0]), "r"(a[1]), "r"(a[2]), "r"(a[3]), "r"(b0), "r"(b1));
}

// f16-accumulator HMMA (QK GEMM): C is 2 f16x2 regs whose packing is exactly
// the A-fragment layout needed for the PV GEMM -> no repack required.
DINLINE void mma16816_h(uint32_t* c, const uint32_t* a, uint32_t b0, uint32_t b1) {
    asm volatile(
        "mma.sync.aligned.m16n8k16.row.col.f16.f16.f16.f16 "
        "{%0,%1}, {%2,%3,%4,%5}, {%6,%7}, {%0,%1};"
        : "+r"(c[0]), "+r"(c[1])
        : "r"(a[0]), "r"(a[1]), "r"(a[2]), "r"(a[3]), "r"(b0), "r"(b1));
}

// sigmoid(score/8) on a packed f16x2 of (score/16):
// p = 0.5 + 0.5*tanh(u); one MUFU + one HFMA2 per two elements.
DINLINE uint32_t sigmoid_h2(uint32_t u) {
    uint32_t t, r;
    const uint32_t H05 = 0x38003800u;  // (0.5, 0.5) f16x2
    asm("tanh.approx.f16x2 %0, %1;" : "=r"(t) : "r"(u));
    asm("fma.rn.f16x2 %0, %1, %2, %2;" : "=r"(r) : "r"(t), "r"(H05));
    return r;
}

DINLINE uint32_t packh2(float a, float b) {
    __half2 h = __floats2half2_rn(a, b);
    return *reinterpret_cast<uint32_t*>(&h);
}

// ---------------- problem constants ----------------
// B=4, H=16, S=2048, D=64.  64 heads x 8 q-tiles of 256 rows = 512 CTAs.
// 16 warps/CTA, M=16 q-rows per warp (R6 champion structure).
static constexpr int S_LEN  = 2048;
static constexpr int D_DIM  = 64;
static constexpr int QTILE  = 256;
static constexpr int KTILE  = 64;
static constexpr int NKT    = S_LEN / KTILE;   // 32
static constexpr int NWARP  = 16;
static constexpr int NTHR   = NWARP * 32;      // 512

// SMEM (halves, row stride 72 => 144B rows, conflict-free for ldmatrix)
static constexpr int STRIDE   = 72;
static constexpr int TILE_B   = KTILE * STRIDE * 2;      // 9216 bytes (one 64x64 f16 tile)
static constexpr int BUF_B    = 2 * TILE_B;              // K + V per stage: 18432
static constexpr int SMEM_BYTES = 2 * BUF_B;             // 36864 (double buffer; Q staging reuses)

__global__ void __launch_bounds__(NTHR, 1) sigattn_kernel(
    const float* __restrict__ gq, const float* __restrict__ gk,
    const float* __restrict__ gv, float* __restrict__ gout)
{
    extern __shared__ char smem[];
    const uint32_t sb = smem_u32(smem);
    const int tid  = threadIdx.x;
    const int wid  = tid >> 5;
    const int lane = tid & 31;

    const int bx = blockIdx.x;
    const int qt = bx & 7;           // q-tile within head
    const int bh = bx >> 3;          // flattened (b,h)
    const size_t head_base = (size_t)bh * S_LEN * D_DIM;
    const float* qb = gq + head_base + (size_t)qt * QTILE * D_DIM;
    const float* kb = gk + head_base;
    const float* vb = gv + head_base;
    float*       ob = gout + head_base + (size_t)qt * QTILE * D_DIM;

    // ---- stage Q (fp32 -> f16, pre-scaled by 1/16) into SMEM ----
    {
        const float SC = 0.0625f;           // folds the /8 sdpa scale and /2 of tanh
        int row = tid >> 1;                 // 0..255
        int c0  = (tid & 1) * 32;           // 0 or 32
        const float4* src = reinterpret_cast<const float4*>(qb + (size_t)row * D_DIM + c0);
        uint32_t* dst = reinterpret_cast<uint32_t*>(smem) + (row * STRIDE + c0) / 2;
        #pragma unroll
        for (int i = 0; i < 8; i++) {
            float4 f = src[i];
            dst[2 * i]     = packh2(f.x * SC, f.y * SC);
            dst[2 * i + 1] = packh2(f.z * SC, f.w * SC);
        }
    }
    __syncthreads();

    const int idx = lane & 15;
    const int seg = lane >> 4;          // 0/1

    // Q fragments: qf[kstep][4] regs, warp rows 16*wid .. +15
    uint32_t qf[4][4];
    #pragma unroll
    for (int s = 0; s < 4; s++) {
        uint32_t addr = sb + (uint32_t)(((16 * wid + idx) * STRIDE) + 16 * s + 8 * seg) * 2;
        ldsm_x4(qf[s][0], qf[s][1], qf[s][2], qf[s][3], addr);
    }
    __syncthreads();   // Q fully in registers before K/V overwrite SMEM

    // per-thread K/V gmem/smem coordinates (64x64 tile, 512 threads)
    const int kvrow = tid >> 3;             // 0..63
    const int kvc0  = (tid & 7) * 8;        // 0..56
    const int kv_soff = (kvrow * STRIDE + kvc0) / 2;   // u32 index into tile
    const size_t kv_gbase = (size_t)kvrow * D_DIM + kvc0;

    // ---- preload tile 0 into buffer 0 ----
    {
        const float4* ksrc = reinterpret_cast<const float4*>(kb + kv_gbase);
        const float4* vsrc = reinterpret_cast<const float4*>(vb + kv_gbase);
        float4 k0 = ksrc[0], k1 = ksrc[1];
        float4 v0 = vsrc[0], v1 = vsrc[1];
        uint32_t* kd = reinterpret_cast<uint32_t*>(smem) + kv_soff;
        uint32_t* vd = reinterpret_cast<uint32_t*>(smem + TILE_B) + kv_soff;
        kd[0] = packh2(k0.x, k0.y); kd[1] = packh2(k0.z, k0.w);
        kd[2] = packh2(k1.x, k1.y); kd[3] = packh2(k1.z, k1.w);
        vd[0] = packh2(v0.x, v0.y); vd[1] = packh2(v0.z, v0.w);
        vd[2] = packh2(v1.x, v1.y); vd[3] = packh2(v1.z, v1.w);
    }
    __syncthreads();

    // ---- O accumulators: 8 d-tiles x 4 fp32 ----
    float oc[8][4];
    #pragma unroll
    for (int j = 0; j < 8; j++)
        #pragma unroll
        for (int r = 0; r < 4; r++) oc[j][r] = 0.0f;

    // loop-invariant piece of B-side ldmatrix addresses
    const uint32_t lds_base = sb + (uint32_t)((idx * STRIDE + 8 * seg) * 2);

    for (int kt = 0; kt < NKT; kt++) {
        const uint32_t cur_off  = (uint32_t)((kt & 1) * BUF_B);
        const uint32_t next_off = (uint32_t)(((kt + 1) & 1) * BUF_B);

        // ---- prefetch tile kt+1 (fp32 -> f16 in regs); lands during compute ----
        uint32_t kr[4], vr[4];
        {
            int ktn = (kt + 1 < NKT) ? kt + 1 : kt;   // clamp (last-iter data unused)
            size_t gofs = (size_t)ktn * KTILE * D_DIM + kv_gbase;
            const float4* ksrc = reinterpret_cast<const float4*>(kb + gofs);
            const float4* vsrc = reinterpret_cast<const float4*>(vb + gofs);
            float4 k0 = ksrc[0], k1 = ksrc[1];
            float4 v0 = vsrc[0], v1 = vsrc[1];
            kr[0] = packh2(k0.x, k0.y); kr[1] = packh2(k0.z, k0.w);
            kr[2] = packh2(k1.x, k1.y); kr[3] = packh2(k1.z, k1.w);
            vr[0] = packh2(v0.x, v0.y); vr[1] = packh2(v0.z, v0.w);
            vr[2] = packh2(v1.x, v1.y); vr[3] = packh2(v1.z, v1.w);
        }

        // ---- QK: S[16 x 64] = Q @ K^T, f16 accumulators ----
        uint32_t sch[8][2];
        #pragma unroll
        for (int j = 0; j < 8; j++) { sch[j][0] = 0u; sch[j][1] = 0u; }

        #pragma unroll
        for (int s = 0; s < 4; s++) {
            #pragma unroll
            for (int j = 0; j < 4; j++) {   // 16-key groups
                uint32_t r0, r1, r2, r3;
                uint32_t addr = lds_base + cur_off +
                    (uint32_t)((16 * j * STRIDE + 16 * s) * 2);
                ldsm_x4(r0, r1, r2, r3, addr);
                mma16816_h(sch[2 * j],     qf[s], r0, r2);   // keys 16j+0..7
                mma16816_h(sch[2 * j + 1], qf[s], r1, r3);   // keys 16j+8..15
            }
        }

        // ---- sigmoid (f16x2) -> P A-frags directly (no repack) ----
        uint32_t pf[4][4];
        #pragma unroll
        for (int t = 0; t < 4; t++) {
            pf[t][0] = sigmoid_h2(sch[2 * t][0]);       // (q,    keys lo8)
            pf[t][1] = sigmoid_h2(sch[2 * t][1]);       // (q+8,  keys lo8)
            pf[t][2] = sigmoid_h2(sch[2 * t + 1][0]);   // (q,    keys hi8)
            pf[t][3] = sigmoid_h2(sch[2 * t + 1][1]);   // (q+8,  keys hi8)
        }

        // ---- PV: O += P @ V  (fp32 accum) ----
        #pragma unroll
        for (int t = 0; t < 4; t++) {       // key k-steps of 16
            #pragma unroll
            for (int m = 0; m < 4; m++) {   // d pair-of-n8 tiles
                uint32_t r0, r1, r2, r3;
                uint32_t addr = lds_base + cur_off + (uint32_t)TILE_B +
                    (uint32_t)((16 * t * STRIDE + 16 * m) * 2);
                ldsm_x4_trans(r0, r1, r2, r3, addr);
                mma16816(oc[2 * m],     pf[t], r0, r1);
                mma16816(oc[2 * m + 1], pf[t], r2, r3);
            }
        }

        __syncthreads();   // all warps done reading before overwriting other buffer

        // ---- store prefetched tile kt+1 into the other buffer ----
        if (kt + 1 < NKT) {
            uint32_t* kd = reinterpret_cast<uint32_t*>(smem + next_off) + kv_soff;
            uint32_t* vd = reinterpret_cast<uint32_t*>(smem + next_off + TILE_B) + kv_soff;
            kd[0] = kr[0]; kd[1] = kr[1]; kd[2] = kr[2]; kd[3] = kr[3];
            vd[0] = vr[0]; vd[1] = vr[1]; vd[2] = vr[2]; vd[3] = vr[3];
        }
        __syncthreads();
    }

    // ---- epilogue: write O (fp32) ----
    {
        const int g  = lane >> 2;
        const int tg = lane & 3;
        const int r0 = 16 * wid + g;
        const int r1 = r0 + 8;
        #pragma unroll
        for (int j = 0; j < 8; j++) {
            int c = 8 * j + 2 * tg;
            *reinterpret_cast<float2*>(ob + (size_t)r0 * D_DIM + c) =
                make_float2(oc[j][0], oc[j][1]);
            *reinterpret_cast<float2*>(ob + (size_t)r1 * D_DIM + c) =
                make_float2(oc[j][2], oc[j][3]);
        }
    }
}

extern "C" void kernel_launch(void* const* d_in, const int* in_sizes, int n_in,
                              void* d_out, int out_size) {
    (void)in_sizes; (void)n_in; (void)out_size;
    const float* q = (const float*)d_in[0];
    const float* k = (const float*)d_in[1];
    const float* v = (const float*)d_in[2];
    float* out = (float*)d_out;

    cudaFuncSetAttribute(sigattn_kernel,
                         cudaFuncAttributeMaxDynamicSharedMemorySize, SMEM_BYTES);
    sigattn_kernel<<<512, NTHR, SMEM_BYTES>>>(q, k, v, out);
}

// round 14
// speedup vs baseline: 1.2476x; 1.0942x over previous
#include <cuda_runtime.h>
#include <cuda_fp16.h>
#include <cstdint>

#define DINLINE __device__ __forceinline__

// ---------------- helpers ----------------

DINLINE uint32_t smem_u32(const void* p) {
    uint32_t a;
    asm("{ .reg .u64 t; cvta.to.shared.u64 t, %1; cvt.u32.u64 %0, t; }"
        : "=r"(a) : "l"(p));
    return a;
}

DINLINE void ldsm_x4(uint32_t& r0, uint32_t& r1, uint32_t& r2, uint32_t& r3,
                     uint32_t addr) {
    asm volatile("ldmatrix.sync.aligned.m8n8.x4.shared.b16 {%0,%1,%2,%3}, [%4];"
                 : "=r"(r0), "=r"(r1), "=r"(r2), "=r"(r3) : "r"(addr));
}

DINLINE void ldsm_x4_trans(uint32_t& r0, uint32_t& r1, uint32_t& r2, uint32_t& r3,
                           uint32_t addr) {
    asm volatile("ldmatrix.sync.aligned.m8n8.x4.trans.shared.b16 {%0,%1,%2,%3}, [%4];"
                 : "=r"(r0), "=r"(r1), "=r"(r2), "=r"(r3) : "r"(addr));
}

// fp32-accumulator HMMA (PV GEMM)
DINLINE void mma16816(float* c, const uint32_t* a, uint32_t b0, uint32_t b1) {
    asm volatile(
        "mma.sync.aligned.m16n8k16.row.col.f32.f16.f16.f32 "
        "{%0,%1,%2,%3}, {%4,%5,%6,%7}, {%8,%9}, {%0,%1,%2,%3};"
        : "+f"(c[0]), "+f"(c[1]), "+f"(c[2]), "+f"(c[3])
        : "r"(a[0]), "r"(a[1]), "r"(a[2]), "r"(a[3]), "r"(b0), "r"(b1));
}

// f16-accumulator HMMA (QK GEMM): C is 2 f16x2 regs whose packing is exactly
// the A-fragment layout needed for the PV GEMM -> no repack required.
DINLINE void mma16816_h(uint32_t* c, const uint32_t* a, uint32_t b0, uint32_t b1) {
    asm volatile(
        "mma.sync.aligned.m16n8k16.row.col.f16.f16.f16.f16 "
        "{%0,%1}, {%2,%3,%4,%5}, {%6,%7}, {%0,%1};"
        : "+r"(c[0]), "+r"(c[1])
        : "r"(a[0]), "r"(a[1]), "r"(a[2]), "r"(a[3]), "r"(b0), "r"(b1));
}

// sigmoid(score/8) on a packed f16x2 of (score/16):
// p = 0.5 + 0.5*tanh(u); one MUFU + one HFMA2 per two elements.
DINLINE uint32_t sigmoid_h2(uint32_t u) {
    uint32_t t, r;
    const uint32_t H05 = 0x38003800u;  // (0.5, 0.5) f16x2
    asm("tanh.approx.f16x2 %0, %1;" : "=r"(t) : "r"(u));
    asm("fma.rn.f16x2 %0, %1, %2, %2;" : "=r"(r) : "r"(t), "r"(H05));
    return r;
}

DINLINE uint32_t packh2(float a, float b) {
    __half2 h = __floats2half2_rn(a, b);
    return *reinterpret_cast<uint32_t*>(&h);
}

// ---------------- problem constants ----------------
// B=4, H=16, S=2048, D=64.  64 heads x 8 q-tiles of 256 rows = 512 CTAs.
// 16 warps/CTA, M=16 q-rows per warp. The 4 independent 16-key chunks of
// each iteration are processed in a PER-WARP ROTATED order so the 4 warps
// of each SMSP sit at different ldsm/mma phases (crossbar and tensor pipes
// overlap instead of pulsing in lockstep).
static constexpr int S_LEN  = 2048;
static constexpr int D_DIM  = 64;
static constexpr int QTILE  = 256;
static constexpr int KTILE  = 64;
static constexpr int NKT    = S_LEN / KTILE;   // 32
static constexpr int NWARP  = 16;
static constexpr int NTHR   = NWARP * 32;      // 512

// SMEM (halves, row stride 72 => 144B rows, conflict-free for ldmatrix)
static constexpr int STRIDE   = 72;
static constexpr int TILE_B   = KTILE * STRIDE * 2;      // 9216 bytes (one 64x64 f16 tile)
static constexpr int BUF_B    = 2 * TILE_B;              // K + V per stage: 18432
static constexpr int SMEM_BYTES = 2 * BUF_B;             // 36864 (double buffer; Q staging reuses)

__global__ void __launch_bounds__(NTHR, 1) sigattn_kernel(
    const float* __restrict__ gq, const float* __restrict__ gk,
    const float* __restrict__ gv, float* __restrict__ gout)
{
    extern __shared__ char smem[];
    const uint32_t sb = smem_u32(smem);
    const int tid  = threadIdx.x;
    const int wid  = tid >> 5;
    const int lane = tid & 31;

    const int bx = blockIdx.x;
    const int qt = bx & 7;           // q-tile within head
    const int bh = bx >> 3;          // flattened (b,h)
    const size_t head_base = (size_t)bh * S_LEN * D_DIM;
    const float* qb = gq + head_base + (size_t)qt * QTILE * D_DIM;
    const float* kb = gk + head_base;
    const float* vb = gv + head_base;
    float*       ob = gout + head_base + (size_t)qt * QTILE * D_DIM;

    // ---- stage Q (fp32 -> f16, pre-scaled by 1/16) into SMEM ----
    {
        const float SC = 0.0625f;           // folds the /8 sdpa scale and /2 of tanh
        int row = tid >> 1;                 // 0..255
        int c0  = (tid & 1) * 32;           // 0 or 32
        const float4* src = reinterpret_cast<const float4*>(qb + (size_t)row * D_DIM + c0);
        uint32_t* dst = reinterpret_cast<uint32_t*>(smem) + (row * STRIDE + c0) / 2;
        #pragma unroll
        for (int i = 0; i < 8; i++) {
            float4 f = src[i];
            dst[2 * i]     = packh2(f.x * SC, f.y * SC);
            dst[2 * i + 1] = packh2(f.z * SC, f.w * SC);
        }
    }
    __syncthreads();

    const int idx = lane & 15;
    const int seg = lane >> 4;          // 0/1
    const int rot = (wid >> 2) & 3;     // chunk rotation: varies WITHIN each SMSP

    // Q fragments: qf[kstep][4] regs, warp rows 16*wid .. +15
    uint32_t qf[4][4];
    #pragma unroll
    for (int s = 0; s < 4; s++) {
        uint32_t addr = sb + (uint32_t)(((16 * wid + idx) * STRIDE) + 16 * s + 8 * seg) * 2;
        ldsm_x4(qf[s][0], qf[s][1], qf[s][2], qf[s][3], addr);
    }
    __syncthreads();   // Q fully in registers before K/V overwrite SMEM

    // per-thread K/V gmem/smem coordinates (64x64 tile, 512 threads)
    const int kvrow = tid >> 3;             // 0..63
    const int kvc0  = (tid & 7) * 8;        // 0..56
    const int kv_soff = (kvrow * STRIDE + kvc0) / 2;   // u32 index into tile
    const size_t kv_gbase = (size_t)kvrow * D_DIM + kvc0;

    // ---- preload tile 0 into buffer 0 ----
    {
        const float4* ksrc = reinterpret_cast<const float4*>(kb + kv_gbase);
        const float4* vsrc = reinterpret_cast<const float4*>(vb + kv_gbase);
        float4 k0 = ksrc[0], k1 = ksrc[1];
        float4 v0 = vsrc[0], v1 = vsrc[1];
        uint32_t* kd = reinterpret_cast<uint32_t*>(smem) + kv_soff;
        uint32_t* vd = reinterpret_cast<uint32_t*>(smem + TILE_B) + kv_soff;
        kd[0] = packh2(k0.x, k0.y); kd[1] = packh2(k0.z, k0.w);
        kd[2] = packh2(k1.x, k1.y); kd[3] = packh2(k1.z, k1.w);
        vd[0] = packh2(v0.x, v0.y); vd[1] = packh2(v0.z, v0.w);
        vd[2] = packh2(v1.x, v1.y); vd[3] = packh2(v1.z, v1.w);
    }
    __syncthreads();

    // ---- O accumulators: 8 d-tiles x 4 fp32 ----
    float oc[8][4];
    #pragma unroll
    for (int j = 0; j < 8; j++)
        #pragma unroll
        for (int r = 0; r < 4; r++) oc[j][r] = 0.0f;

    // loop-invariant piece of B-side ldmatrix addresses
    const uint32_t lds_base = sb + (uint32_t)((idx * STRIDE + 8 * seg) * 2);

    for (int kt = 0; kt < NKT; kt++) {
        const uint32_t cur_off  = (uint32_t)((kt & 1) * BUF_B);
        const uint32_t next_off = (uint32_t)(((kt + 1) & 1) * BUF_B);

        // ---- prefetch tile kt+1 (fp32 -> f16 in regs); lands during compute ----
        uint32_t kr[4], vr[4];
        {
            int ktn = (kt + 1 < NKT) ? kt + 1 : kt;   // clamp (last-iter data unused)
            size_t gofs = (size_t)ktn * KTILE * D_DIM + kv_gbase;
            const float4* ksrc = reinterpret_cast<const float4*>(kb + gofs);
            const float4* vsrc = reinterpret_cast<const float4*>(vb + gofs);
            float4 k0 = ksrc[0], k1 = ksrc[1];
            float4 v0 = vsrc[0], v1 = vsrc[1];
            kr[0] = packh2(k0.x, k0.y); kr[1] = packh2(k0.z, k0.w);
            kr[2] = packh2(k1.x, k1.y); kr[3] = packh2(k1.z, k1.w);
            vr[0] = packh2(v0.x, v0.y); vr[1] = packh2(v0.z, v0.w);
            vr[2] = packh2(v1.x, v1.y); vr[3] = packh2(v1.z, v1.w);
        }

        // ---- compute, 16-key chunks in per-warp rotated order ----
        #pragma unroll
        for (int tc = 0; tc < 4; tc++) {
            const int t = (tc + rot) & 3;   // this warp's chunk for this step

            // QK for keys 16t..16t+15 (f16 accumulators)
            uint32_t sch0[2] = {0u, 0u};    // keys lo8
            uint32_t sch1[2] = {0u, 0u};    // keys hi8
            #pragma unroll
            for (int s = 0; s < 4; s++) {
                uint32_t r0, r1, r2, r3;
                uint32_t addr = lds_base + cur_off +
                    (uint32_t)((16 * t * STRIDE + 16 * s) * 2);
                ldsm_x4(r0, r1, r2, r3, addr);
                mma16816_h(sch0, qf[s], r0, r2);
                mma16816_h(sch1, qf[s], r1, r3);
            }

            // V fragments issued before the MUFU chain (latency hiding)
            uint32_t vf[4][4];
            #pragma unroll
            for (int m = 0; m < 4; m++) {
                uint32_t addr = lds_base + cur_off + (uint32_t)TILE_B +
                    (uint32_t)((16 * t * STRIDE + 16 * m) * 2);
                ldsm_x4_trans(vf[m][0], vf[m][1], vf[m][2], vf[m][3], addr);
            }

            // sigmoid (f16x2) -> P A-frag directly (no repack)
            uint32_t pf[4];
            pf[0] = sigmoid_h2(sch0[0]);
            pf[1] = sigmoid_h2(sch0[1]);
            pf[2] = sigmoid_h2(sch1[0]);
            pf[3] = sigmoid_h2(sch1[1]);

            // PV: O += P(:,chunk) @ V(chunk,:)  (fp32 accum)
            #pragma unroll
            for (int m = 0; m < 4; m++) {
                mma16816(oc[2 * m],     pf, vf[m][0], vf[m][1]);
                mma16816(oc[2 * m + 1], pf, vf[m][2], vf[m][3]);
            }
        }

        __syncthreads();   // all warps done reading before overwriting other buffer

        // ---- store prefetched tile kt+1 into the other buffer ----
        if (kt + 1 < NKT) {
            uint32_t* kd = reinterpret_cast<uint32_t*>(smem + next_off) + kv_soff;
            uint32_t* vd = reinterpret_cast<uint32_t*>(smem + next_off + TILE_B) + kv_soff;
            kd[0] = kr[0]; kd[1] = kr[1]; kd[2] = kr[2]; kd[3] = kr[3];
            vd[0] = vr[0]; vd[1] = vr[1]; vd[2] = vr[2]; vd[3] = vr[3];
        }
        __syncthreads();
    }

    // ---- epilogue: write O (fp32) ----
    {
        const int g  = lane >> 2;
        const int tg = lane & 3;
        const int r0 = 16 * wid + g;
        const int r1 = r0 + 8;
        #pragma unroll
        for (int j = 0; j < 8; j++) {
            int c = 8 * j + 2 * tg;
            *reinterpret_cast<float2*>(ob + (size_t)r0 * D_DIM + c) =
                make_float2(oc[j][0], oc[j][1]);
            *reinterpret_cast<float2*>(ob + (size_t)r1 * D_DIM + c) =
                make_float2(oc[j][2], oc[j][3]);
        }
    }
}

extern "C" void kernel_launch(void* const* d_in, const int* in_sizes, int n_in,
                              void* d_out, int out_size) {
    (void)in_sizes; (void)n_in; (void)out_size;
    const float* q = (const float*)d_in[0];
    const float* k = (const float*)d_in[1];
    const float* v = (const float*)d_in[2];
    float* out = (float*)d_out;

    cudaFuncSetAttribute(sigattn_kernel,
                         cudaFuncAttributeMaxDynamicSharedMemorySize, SMEM_BYTES);
    sigattn_kernel<<<512, NTHR, SMEM_BYTES>>>(q, k, v, out);
}